// round 17
// baseline (speedup 1.0000x reference)
#include <cuda_runtime.h>
#include <math.h>
#include <float.h>

constexpr int NB = 128, NA = 2, NH = 128, NW = 128;
constexpr int PLANE = NH * NW;
constexpr float THRESH = 0.6f;
constexpr float OBJ_SCALE = 5.0f;
constexpr float LN_MARGIN = 0.55961579f;   // ln(1.75) > ln(5/3)+fastlog-err margin
constexpr float POS_MARGIN = 1.30f;        // > 1.2889 exact positional bound
constexpr int NBLOCKS = 1024;              // 262144 threads * 16 cells
constexpr long long TOTAL_CELLS = (long long)NB * NA * NH * NW;  // 4194304

// Accumulators (zero at module load; reset by last block each run)
__device__ double g_conf2 = 0.0;
__device__ unsigned long long g_cnt = 0ull;   // corrections only (negative)
__device__ float  g_sel = 0.0f;
__device__ unsigned g_done = 0u;

__device__ __forceinline__ float sig_fast(float x) {
    return __fdividef(1.0f, 1.0f + __expf(-x));
}

__global__ void __launch_bounds__(256) k_fused(const float* __restrict__ out,
                                               const float* __restrict__ tgt,
                                               const float* __restrict__ anc,
                                               float* __restrict__ res) {
    int gtid = blockIdx.x * 256 + threadIdx.x;
    int i16 = (gtid & 7) * 16;        // 16 contiguous columns
    int r  = gtid >> 3;
    int j  = r & 127; r >>= 7;        // row
    int a  = r & 1;                   // anchor (block-uniform)
    int b  = r >> 1;                  // batch  (block-uniform)

    // ---- conf loads first: 4 front-batched float4 ----
    const float* pbase = out + ((size_t)(b * 10 + a * 5) * NH + j) * NW + i16;
    const float* pconf = pbase + 4 * (size_t)PLANE;
    float4 c0 = *(const float4*)(pconf);
    float4 c1 = *(const float4*)(pconf + 4);
    float4 c2 = *(const float4*)(pconf + 8);
    float4 c3 = *(const float4*)(pconf + 12);

    // ---- band membership from target alone ----
    float4 t = __ldg((const float4*)(tgt + b * 4));     // warp-broadcast
    float gx = t.x * (float)NW, gy = t.y * (float)NH;
    float gw = t.z * (float)NW, gh = t.w * (float)NH;

    float fj = (float)j;
    float gxlo = gx - POS_MARGIN * gw - 1.0f, gxhi = gx + POS_MARGIN * gw;
    bool rowok = (fj > gy - POS_MARGIN * gh - 1.0f) && (fj < gy + POS_MARGIN * gh);
    int  gyi = (int)gy;
    int  colk = (int)gx - i16;
    bool maybe_own = ((unsigned)colk < 16u) & (gyi == j);   // gt cell in my window?

    // per-8-chunk column overlap
    bool colokA = ((float)(i16 + 7)  > gxlo) && ((float)i16        < gxhi);
    bool colokB = ((float)(i16 + 15) > gxlo) && ((float)(i16 + 8)  < gxhi);
    bool bandA = rowok & colokA;
    bool bandB = rowok & colokB;

    // ---- hot: unconditional conf^2 over 16 cells ----
    float pc16[16] = {c0.x,c0.y,c0.z,c0.w, c1.x,c1.y,c1.z,c1.w,
                      c2.x,c2.y,c2.z,c2.w, c3.x,c3.y,c3.z,c3.w};
    float conf2f = 0.0f;
    #pragma unroll
    for (int k = 0; k < 16; k++) {
        float rr = sig_fast(pc16[k]);
        conf2f += rr * rr;
    }

    // ---- band path ----
    if (bandA | bandB | maybe_own) {
        float a0w = __ldg(anc + 0), a0h = __ldg(anc + 1);
        float a1w = __ldg(anc + 2), a1h = __ldg(anc + 3);
        float aw = a ? a1w : a0w;
        float ah = a ? a1h : a0h;
        float ga = gw * gh;
        float cc = __logf(__fdividef(ga, aw * ah));

        int kx = -1;
        if (maybe_own) {
            float i0v = fminf(gw, a0w) * fminf(gh, a0h);
            float u0v = ga + 1e-16f + a0w * a0h - i0v;
            float i1v = fminf(gw, a1w) * fminf(gh, a1h);
            float u1v = ga + 1e-16f + a1w * a1h - i1v;
            int best = (i1v * u0v > i0v * u1v) ? 1 : 0;
            if (best == a) kx = colk;
        }

        float gxm = gx - gw * 0.5f, gxM = gx + gw * 0.5f;
        float gym = gy - gh * 0.5f, gyM = gy + gh * 0.5f;
        int cnt = 0;

        // two sequential 8-wide chunks (register arrays reused)
        #pragma unroll
        for (int cchunk = 0; cchunk < 2; cchunk++) {
            bool cb = cchunk ? bandB : bandA;
            int  co = cchunk * 8;
            int  ckx = kx - co;                    // [0,8) iff this chunk owns
            bool cown = (unsigned)ckx < 8u;
            if (!(cb | cown)) continue;

            const float* pch = pbase + co;
            float4 w0 = *(const float4*)(pch + 2 * (size_t)PLANE);
            float4 w1 = *(const float4*)(pch + 2 * (size_t)PLANE + 4);
            float4 h0 = *(const float4*)(pch + 3 * (size_t)PLANE);
            float4 h1 = *(const float4*)(pch + 3 * (size_t)PLANE + 4);
            float pw8[8] = {w0.x,w0.y,w0.z,w0.w,w1.x,w1.y,w1.z,w1.w};
            float ph8[8] = {h0.x,h0.y,h0.z,h0.w,h1.x,h1.y,h1.z,h1.w};

            bool pass[8];
            bool anyp = false;
            #pragma unroll
            for (int k = 0; k < 8; k++) {
                pass[k] = cb && (fabsf(pw8[k] + ph8[k] - cc) < LN_MARGIN);
                anyp |= pass[k];
            }
            if (!(anyp | cown)) continue;

            float4 x0 = *(const float4*)(pch);
            float4 x1 = *(const float4*)(pch + 4);
            float4 y0 = *(const float4*)(pch + (size_t)PLANE);
            float4 y1 = *(const float4*)(pch + (size_t)PLANE + 4);
            float px8[8] = {x0.x,x0.y,x0.z,x0.w,x1.x,x1.y,x1.z,x1.w};
            float py8[8] = {y0.x,y0.y,y0.z,y0.w,y1.x,y1.y,y1.z,y1.w};

            #pragma unroll
            for (int k = 0; k < 8; k++) {         // compile-time indices
                bool is_excl = (k == ckx);
                if (pass[k] | is_excl) {
                    float px = sig_fast(px8[k]) + (float)(i16 + co + k);
                    float py = sig_fast(py8[k]) + fj;
                    float pw = __expf(pw8[k]) * aw;
                    float ph = __expf(ph8[k]) * ah;
                    float mx = fminf(px - pw * 0.5f, gxm);
                    float Mx = fmaxf(px + pw * 0.5f, gxM);
                    float my = fminf(py - ph * 0.5f, gym);
                    float My = fmaxf(py + ph * 0.5f, gyM);
                    float cw = pw + gw - (Mx - mx);
                    float ch = ph + gh - (My - my);
                    float carea = cw * ch;
                    float uarea = pw * ph + ga - carea;
                    bool noobj = (cw <= 0.0f) || (ch <= 0.0f) ||
                                 (carea <= THRESH * uarea);
                    if ((pass[k] && !noobj) || is_excl) {
                        float rr = sig_fast(pc16[co + k]);   // exact cancel
                        conf2f -= rr * rr;
                        cnt--;
                    }
                    if (is_excl) {
                        float tscale = 2.0f - t.z * t.w;
                        float xs = sig_fast(px8[k]);
                        float ys = sig_fast(py8[k]);
                        float cs = sig_fast(pc16[co + k]);
                        float txv = gx - floorf(gx), tyv = gy - floorf(gy);
                        float twv = __logf(__fdividef(gw, aw) + 1e-16f);
                        float thv = __logf(__fdividef(gh, ah) + 1e-16f);
                        float dx = (xs - txv) * tscale, dy = (ys - tyv) * tscale;
                        float dw = (pw8[k] - twv) * tscale;
                        float dh = (ph8[k] - thv) * tscale;
                        // rare (<=1 thread/batch): direct global atomic
                        atomicAdd(&g_sel, (dx*dx + dy*dy + dw*dw + dh*dh
                              + OBJ_SCALE * (cs - 1.0f) * (cs - 1.0f))
                              * (1.0f / (float)NB));
                    }
                }
            }
        }
        // rare: direct global atomic
        if (cnt != 0)
            atomicAdd(&g_cnt, (unsigned long long)(long long)cnt);
    }

    // ---- single-quantity block reduce ----
    #pragma unroll
    for (int o = 16; o > 0; o >>= 1)
        conf2f += __shfl_down_sync(0xffffffffu, conf2f, o);

    __shared__ float sh_c2[8];
    int lane = threadIdx.x & 31, wrp = threadIdx.x >> 5;
    if (lane == 0) sh_c2[wrp] = conf2f;
    __syncthreads();
    if (wrp == 0) {
        float v = (lane < 8) ? sh_c2[lane] : 0.0f;
        #pragma unroll
        for (int o = 4; o > 0; o >>= 1)
            v += __shfl_down_sync(0xffffffffu, v, o);
        if (lane == 0) {
            atomicAdd(&g_conf2, (double)v);
            __threadfence();
            unsigned old = atomicAdd(&g_done, 1u);
            if (old == (unsigned)(NBLOCKS - 1)) {
                __threadfence();
                double n_noobj = (double)(TOTAL_CELLS + (long long)g_cnt);
                res[0] = g_sel + (float)(g_conf2 / n_noobj);
                g_conf2 = 0.0; g_cnt = 0ull; g_sel = 0.0f; g_done = 0u;
            }
        }
    }
}

extern "C" void kernel_launch(void* const* d_in, const int* in_sizes, int n_in,
                              void* d_out, int out_size) {
    const float* out = (const float*)d_in[0];   // (128, 10, 128, 128)
    const float* tgt = (const float*)d_in[1];   // (128, 4)
    const float* anc = (const float*)d_in[2];   // (2, 2)
    float* res = (float*)d_out;

    k_fused<<<NBLOCKS, 256>>>(out, tgt, anc, res);
}